// round 11
// baseline (speedup 1.0000x reference)
#include <cuda_runtime.h>
#include <cstdint>

#define LL    320
#define DD    128
#define NBINS 32
#define EPSF  1e-8f

#define Z_ELEMS (LL*LL*DD)     // 13,107,200
#define P_ELEMS (3*LL*LL)      //    307,200
#define CD_ELEMS (LL*LL)       //    102,400
// output layout: [z | pxyz | cadistavg], all f32

// ---- cadistavg: 32x32 tiles, upper triangle, i-split x4, 2x2 microtile
#define NT2 10                  // 320/32
#define C_TILES 55              // NT2*(NT2+1)/2
#define ICHUNKS 4
#define ISPAN  (LL/ICHUNKS)     // 80
#define C_BLOCKS (C_TILES*ICHUNKS)   // 220
#define CCH 8                   // i-rows staged per chunk

// ---- z / p stream
#define ZB 3200                 // 3200*256*4 f4 = Z_ELEMS/4
#define PB 300                  // 300*256 f4 = P_ELEMS/4
#define ZUNROLL 4

#define GRID1 (C_BLOCKS + ZB + PB)   // 3720
// C blocks interleaved: grid positions 15, 31, ..., 16*219+15 = 3519

// per-chunk partial sums of cadistavg (reduced by kernel 2)
__device__ float g_cd_part[ICHUNKS * CD_ELEMS];   // 1.6 MB static scratch

__device__ __forceinline__ float fsqrt_approx(float x) {
    float y;
    asm("sqrt.approx.f32 %0, %1;" : "=f"(y) : "f"(x));
    return y;
}

__device__ __forceinline__ float dist3(float4 a, float4 b) {
    float dx = a.x - b.x, dy = a.y - b.y, dz = a.z - b.z;
    return fsqrt_approx(fmaf(dx, dx, fmaf(dy, dy, fmaf(dz, dz, EPSF))));
}

// ============ kernel 1: interleaved C partials + z stream + pxyz ============
__global__ __launch_bounds__(256)
void fused1(const int* __restrict__ residx,
            const int* __restrict__ mask,        // bool as int32
            const float* __restrict__ emb,
            const float4* __restrict__ pair4,
            const float* __restrict__ predxyz,
            const float* __restrict__ maskdiag,
            float* __restrict__ out)
{
    const int blk = blockIdx.x;
    const int tid = threadIdx.x;

    const int  cslot = blk >> 4;
    const bool isC   = ((blk & 15) == 15) && (cslot < C_BLOCKS);

    if (isC) {
        // ---- cadistavg partial: 32x32 (j,k) tile over one i-chunk of 80
        __shared__ float4 sK[CCH][32];
        __shared__ float4 sJ[CCH][32];

        const int tile = cslot >> 2;        // 0..54
        const int chnk = cslot & 3;         // i-chunk 0..3

        int a = 0, t = tile;                // tile -> (a, b2), a <= b2
        while (t >= NT2 - a) { t -= NT2 - a; a++; }
        const int b2 = a + t;
        const int jt = a * 32;
        const int kt = b2 * 32;

        // staging role: 128 threads per tile-side, float2 (2 cols) each
        const int side = tid >> 7;          // 0 = K cols, 1 = J cols
        const int rem  = tid & 127;
        const int sii  = rem >> 4;          // i-row within chunk (0..7)
        const int scol = (side ? jt : kt) + 2 * (rem & 15);

        // compute role: 2x2 microtile
        const int tx = tid & 15;            // k, k+16
        const int ty = tid >> 4;            // j, j+16

        float v00 = 0.f, v01 = 0.f, v10 = 0.f, v11 = 0.f;

        const int ibeg = chnk * ISPAN;
        for (int i0 = ibeg; i0 < ibeg + ISPAN; i0 += CCH) {
            const int gi = i0 + sii;
            const float2 px = *(const float2*)(predxyz + 0 * LL * LL + gi * LL + scol);
            const float2 py = *(const float2*)(predxyz + 1 * LL * LL + gi * LL + scol);
            const float2 pz = *(const float2*)(predxyz + 2 * LL * LL + gi * LL + scol);
            const float2 m2 = *(const float2*)(maskdiag + gi * LL + scol);

            __syncthreads();                // previous chunk's compute done
            {
                float4* dst = side ? &sJ[sii][scol - jt] : &sK[sii][scol - kt];
                dst[0] = make_float4(px.x * m2.x, py.x * m2.x, pz.x * m2.x, 0.f);
                dst[1] = make_float4(px.y * m2.y, py.y * m2.y, pz.y * m2.y, 0.f);
            }
            __syncthreads();                // chunk staged

            #pragma unroll
            for (int ii = 0; ii < CCH; ii++) {
                const float4 ka = sK[ii][tx];
                const float4 kb = sK[ii][tx + 16];
                const float4 ja = sJ[ii][ty];
                const float4 jb = sJ[ii][ty + 16];
                v00 += dist3(ka, ja);
                v01 += dist3(kb, ja);
                v10 += dist3(ka, jb);
                v11 += dist3(kb, jb);
            }
        }

        float* part = g_cd_part + chnk * CD_ELEMS;
        const float s = 1.0f / LL;
        part[(jt + ty)      * LL + kt + tx]      = v00 * s;
        part[(jt + ty)      * LL + kt + tx + 16] = v01 * s;
        part[(jt + ty + 16) * LL + kt + tx]      = v10 * s;
        part[(jt + ty + 16) * LL + kt + tx + 16] = v11 * s;
        if (a != b2) {                       // mirror (symmetric)
            part[(kt + tx)      * LL + jt + ty]      = v00 * s;
            part[(kt + tx + 16) * LL + jt + ty]      = v01 * s;
            part[(kt + tx)      * LL + jt + ty + 16] = v10 * s;
            part[(kt + tx + 16) * LL + jt + ty + 16] = v11 * s;
        }
        return;
    }

    // stream index with interleaved C blocks removed
    const int sidx = blk - min((blk + 1) >> 4, C_BLOCKS);

    if (sidx < ZB) {
        // ---- z = pair_feats + emb[idx]
        const float4* e4 = (const float4*)emb;
        float4* out4 = (float4*)out;
        const int stride = ZB * 256;
        int e = sidx * 256 + tid;                // float4 index into z
        #pragma unroll
        for (int k = 0; k < ZUNROLL; k++, e += stride) {
            const int p = e >> 5;                // pair index (32 f4 per pair)
            const int s = e & 31;                // f4 slot within D=128
            const int i = p / LL;
            const int j = p - i * LL;

            int m   = mask[i] & mask[j];
            int dif = residx[j] - residx[i];
            dif = min(max(dif, -NBINS), NBINS) + (NBINS + 1);
            const int idx = m ? dif : 0;

            float4 ev = e4[idx * (DD / 4) + s];
            float4 pv = pair4[e];
            out4[e] = make_float4(pv.x + ev.x, pv.y + ev.y,
                                  pv.z + ev.z, pv.w + ev.w);
        }
    } else {
        // ---- pxyz = predxyz * maskdiag
        const int e = (sidx - ZB) * 256 + tid;   // < 76800
        const float4* pr4 = (const float4*)predxyz;
        const float4* md4 = (const float4*)maskdiag;
        float4 pv = pr4[e];
        float4 mv = md4[e % (LL * LL / 4)];
        ((float4*)(out + Z_ELEMS))[e] =
            make_float4(pv.x * mv.x, pv.y * mv.y, pv.z * mv.z, pv.w * mv.w);
    }
}

// ============ kernel 2: reduce the 4 chunk partials (float4-wide) ============
__global__ __launch_bounds__(256)
void cd_reduce(float* __restrict__ out)
{
    const int e = blockIdx.x * 256 + threadIdx.x;   // float4 index < 25600
    const float4* p = (const float4*)g_cd_part;
    const float4 s0 = p[e];
    const float4 s1 = p[e + CD_ELEMS / 4];
    const float4 s2 = p[e + 2 * (CD_ELEMS / 4)];
    const float4 s3 = p[e + 3 * (CD_ELEMS / 4)];
    ((float4*)(out + Z_ELEMS + P_ELEMS))[e] =
        make_float4(s0.x + s1.x + s2.x + s3.x,
                    s0.y + s1.y + s2.y + s3.y,
                    s0.z + s1.z + s2.z + s3.z,
                    s0.w + s1.w + s2.w + s3.w);
}

extern "C" void kernel_launch(void* const* d_in, const int* in_sizes, int n_in,
                              void* d_out, int out_size) {
    const int*    residx   = (const int*)d_in[0];
    const int*    mask     = (const int*)d_in[1];
    const float*  emb      = (const float*)d_in[2];
    const float4* pair4    = (const float4*)d_in[3];
    const float*  predxyz  = (const float*)d_in[4];
    const float*  maskdiag = (const float*)d_in[5];
    float*        out      = (float*)d_out;

    fused1<<<GRID1, 256>>>(residx, mask, emb, pair4, predxyz, maskdiag, out);
    cd_reduce<<<CD_ELEMS / 4 / 256, 256>>>(out);
}

// round 12
// speedup vs baseline: 1.5461x; 1.5461x over previous
#include <cuda_runtime.h>
#include <cstdint>

#define LL    320
#define DD    128
#define NBINS 32
#define EPSF  1e-8f

#define Z_ELEMS (LL*LL*DD)     // 13,107,200
#define P_ELEMS (3*LL*LL)      //    307,200
#define CD_ELEMS (LL*LL)       //    102,400
// output layout: [z | pxyz | cadistavg], all f32

// ---- cadistavg: 32x32 tiles, upper triangle, i-split x8, 2x2 microtile
#define NT2 10                  // 320/32
#define C_TILES 55              // NT2*(NT2+1)/2
#define ICHUNKS 8
#define ISPAN  (LL/ICHUNKS)     // 40
#define C_BLOCKS (C_TILES*ICHUNKS)   // 440
#define CCH 8                   // i-rows staged per chunk
#define TILE_SZ 1024            // 32*32 partial elems per tile

// ---- z / p stream
#define ZB 3200                 // 3200*256*4 f4 = Z_ELEMS/4
#define PB 300                  // 300*256 f4 = P_ELEMS/4
#define ZUNROLL 4

#define GRID1 (C_BLOCKS + ZB + PB)   // 3940

// compact per-chunk partials: [chunk][tile][32*32]
__device__ float g_cd_part[ICHUNKS * C_TILES * TILE_SZ];   // 1.8 MB
__device__ int   g_tile_cnt[C_TILES];                      // zero-init; self-resetting

__device__ __forceinline__ float fsqrt_approx(float x) {
    float y;
    asm("sqrt.approx.f32 %0, %1;" : "=f"(y) : "f"(x));
    return y;
}

__device__ __forceinline__ float dist3(float4 a, float4 b) {
    float dx = a.x - b.x, dy = a.y - b.y, dz = a.z - b.z;
    return fsqrt_approx(fmaf(dx, dx, fmaf(dy, dy, fmaf(dz, dz, EPSF))));
}

// ============ single main kernel: C partials (front) + z stream + pxyz ============
__global__ __launch_bounds__(256)
void fused1(const int* __restrict__ residx,
            const int* __restrict__ mask,        // bool as int32
            const float* __restrict__ emb,
            const float4* __restrict__ pair4,
            const float* __restrict__ predxyz,
            const float* __restrict__ maskdiag,
            float* __restrict__ out)
{
    const int blk = blockIdx.x;
    const int tid = threadIdx.x;

    if (blk < C_BLOCKS) {
        // ---- cadistavg partial: 32x32 (j,k) tile over one i-chunk of 40
        __shared__ float4 sK[CCH][32];
        __shared__ float4 sJ[CCH][32];
        __shared__ int    sLast;

        const int tile = blk >> 3;          // 0..54
        const int chnk = blk & 7;           // i-chunk 0..7

        int a = 0, t = tile;                // tile -> (a, b2), a <= b2
        while (t >= NT2 - a) { t -= NT2 - a; a++; }
        const int b2 = a + t;
        const int jt = a * 32;
        const int kt = b2 * 32;

        // staging role: 128 threads per tile-side, float2 (2 cols) each
        const int side = tid >> 7;          // 0 = K cols, 1 = J cols
        const int rem  = tid & 127;
        const int sii  = rem >> 4;          // i-row within chunk (0..7)
        const int scol = (side ? jt : kt) + 2 * (rem & 15);

        // compute role: 2x2 microtile
        const int tx = tid & 15;            // k, k+16
        const int ty = tid >> 4;            // j, j+16

        float v00 = 0.f, v01 = 0.f, v10 = 0.f, v11 = 0.f;

        const int ibeg = chnk * ISPAN;
        for (int i0 = ibeg; i0 < ibeg + ISPAN; i0 += CCH) {
            const int gi = i0 + sii;
            const float2 px = *(const float2*)(predxyz + 0 * LL * LL + gi * LL + scol);
            const float2 py = *(const float2*)(predxyz + 1 * LL * LL + gi * LL + scol);
            const float2 pz = *(const float2*)(predxyz + 2 * LL * LL + gi * LL + scol);
            const float2 m2 = *(const float2*)(maskdiag + gi * LL + scol);

            __syncthreads();                // previous chunk's compute done
            {
                float4* dst = side ? &sJ[sii][scol - jt] : &sK[sii][scol - kt];
                dst[0] = make_float4(px.x * m2.x, py.x * m2.x, pz.x * m2.x, 0.f);
                dst[1] = make_float4(px.y * m2.y, py.y * m2.y, pz.y * m2.y, 0.f);
            }
            __syncthreads();                // chunk staged

            #pragma unroll
            for (int ii = 0; ii < CCH; ii++) {
                const float4 ka = sK[ii][tx];
                const float4 kb = sK[ii][tx + 16];
                const float4 ja = sJ[ii][ty];
                const float4 jb = sJ[ii][ty + 16];
                v00 += dist3(ka, ja);
                v01 += dist3(kb, ja);
                v10 += dist3(ka, jb);
                v11 += dist3(kb, jb);
            }
        }

        // write compact partial (no mirror here)
        float* part = g_cd_part + (chnk * C_TILES + tile) * TILE_SZ;
        part[ ty       * 32 + tx     ] = v00;
        part[ ty       * 32 + tx + 16] = v01;
        part[(ty + 16) * 32 + tx     ] = v10;
        part[(ty + 16) * 32 + tx + 16] = v11;

        // release my stores, then count arrivals; 8th block reduces the tile
        __threadfence();
        __syncthreads();
        if (tid == 0)
            sLast = (atomicAdd(&g_tile_cnt[tile], 1) == ICHUNKS - 1);
        __syncthreads();

        if (sLast) {
            __threadfence();                 // acquire other chunks' partials
            float* cd = out + Z_ELEMS + P_ELEMS;
            const float s = 1.0f / LL;
            #pragma unroll
            for (int q = 0; q < 4; q++) {
                const int jj = ty + (q >> 1) * 16;
                const int kk = tx + (q & 1) * 16;
                const float* p0 = g_cd_part + tile * TILE_SZ + jj * 32 + kk;
                float sum = 0.f;
                #pragma unroll
                for (int c = 0; c < ICHUNKS; c++)
                    sum += p0[c * (C_TILES * TILE_SZ)];
                sum *= s;
                cd[(jt + jj) * LL + (kt + kk)] = sum;
                if (a != b2)
                    cd[(kt + kk) * LL + (jt + jj)] = sum;   // symmetric mirror
            }
            if (tid == 0)
                g_tile_cnt[tile] = 0;        // reset for next graph replay
        }

    } else if (blk < C_BLOCKS + ZB) {
        // ---- z = pair_feats + emb[idx]
        const float4* e4 = (const float4*)emb;
        float4* out4 = (float4*)out;
        const int stride = ZB * 256;
        int e = (blk - C_BLOCKS) * 256 + tid;    // float4 index into z
        #pragma unroll
        for (int k = 0; k < ZUNROLL; k++, e += stride) {
            const int p = e >> 5;                // pair index (32 f4 per pair)
            const int s = e & 31;                // f4 slot within D=128
            const int i = p / LL;
            const int j = p - i * LL;

            int m   = mask[i] & mask[j];
            int dif = residx[j] - residx[i];
            dif = min(max(dif, -NBINS), NBINS) + (NBINS + 1);
            const int idx = m ? dif : 0;

            float4 ev = e4[idx * (DD / 4) + s];
            float4 pv = pair4[e];
            out4[e] = make_float4(pv.x + ev.x, pv.y + ev.y,
                                  pv.z + ev.z, pv.w + ev.w);
        }
    } else {
        // ---- pxyz = predxyz * maskdiag
        const int e = (blk - C_BLOCKS - ZB) * 256 + tid;   // < 76800
        const float4* pr4 = (const float4*)predxyz;
        const float4* md4 = (const float4*)maskdiag;
        float4 pv = pr4[e];
        float4 mv = md4[e % (LL * LL / 4)];
        ((float4*)(out + Z_ELEMS))[e] =
            make_float4(pv.x * mv.x, pv.y * mv.y, pv.z * mv.z, pv.w * mv.w);
    }
}

extern "C" void kernel_launch(void* const* d_in, const int* in_sizes, int n_in,
                              void* d_out, int out_size) {
    const int*    residx   = (const int*)d_in[0];
    const int*    mask     = (const int*)d_in[1];
    const float*  emb      = (const float*)d_in[2];
    const float4* pair4    = (const float4*)d_in[3];
    const float*  predxyz  = (const float*)d_in[4];
    const float*  maskdiag = (const float*)d_in[5];
    float*        out      = (float*)d_out;

    fused1<<<GRID1, 256>>>(residx, mask, emb, pair4, predxyz, maskdiag, out);
}